// round 2
// baseline (speedup 1.0000x reference)
#include <cuda_runtime.h>

#define Bt 64
#define NPt 1024
#define Nt 65536
#define Kn 10
#define SLOPEf 0.01f

// ---------------- scratch (device globals; no allocation allowed) ----------------
__device__ __align__(16) float g_f4[Nt * 4];      // xx features
__device__ float g_sq0[Nt];
__device__ float g_u[Nt * 64];                    // xx@(Wtop-Wbot)+b1a
__device__ float g_v[Nt * 64];                    // xx@Wbot
__device__ __align__(16) float g_x1[Nt * 64];
__device__ float g_sq1[Nt];
__device__ int   g_idx1[Nt * Kn];
__device__ int   g_idx2[Nt * Kn];
__device__ __align__(16) float g_P[Nt * 128];     // x1@(W2top-W2bot)+b2
__device__ __align__(16) float g_Q[Nt * 128];     // x1@W2bot
__device__ float g_msum[Bt * 4 * 192];            // per-(batch,sub) partial sums

__device__ __forceinline__ float lrelu(float v) { return v >= 0.f ? v : SLOPEf * v; }

// ---------------- K0: per-point precompute (xx, sq0, u, v) ----------------
__global__ void k0_pre(const float* __restrict__ x, const float* __restrict__ pos,
                       const float* __restrict__ w1a, const float* __restrict__ b1a) {
    int gw = (blockIdx.x * blockDim.x + threadIdx.x) >> 5;   // warp per point
    int lane = threadIdx.x & 31;
    int i = gw;
    if (i >= Nt) return;
    float f0 = x[i];
    float f1 = pos[3 * i + 0];
    float f2 = pos[3 * i + 1];
    float f3 = pos[3 * i + 2];
    if (lane == 0) {
        ((float4*)g_f4)[i] = make_float4(f0, f1, f2, f3);
        g_sq0[i] = f0 * f0 + f1 * f1 + f2 * f2 + f3 * f3;
    }
#pragma unroll
    for (int h = 0; h < 2; h++) {
        int o = lane + 32 * h;
        float wt0 = w1a[0 * 64 + o], wt1 = w1a[1 * 64 + o], wt2 = w1a[2 * 64 + o], wt3 = w1a[3 * 64 + o];
        float wb0 = w1a[4 * 64 + o], wb1 = w1a[5 * 64 + o], wb2 = w1a[6 * 64 + o], wb3 = w1a[7 * 64 + o];
        float vv = f0 * wb0 + f1 * wb1 + f2 * wb2 + f3 * wb3;
        float uu = f0 * (wt0 - wb0) + f1 * (wt1 - wb1) + f2 * (wt2 - wb2) + f3 * (wt3 - wb3) + b1a[o];
        g_u[i * 64 + o] = uu;
        g_v[i * 64 + o] = vv;
    }
}

// ---------------- K1: KNN on 4-dim xx ----------------
__global__ void __launch_bounds__(256) k1_knn1() {
    __shared__ float4 sf[NPt];
    __shared__ float  ssq[NPt];
    int b = blockIdx.x >> 2, rb = blockIdx.x & 3;
    int pb = b * NPt;
    for (int t = threadIdx.x; t < NPt; t += 256) {
        sf[t] = ((const float4*)g_f4)[pb + t];
        ssq[t] = g_sq0[pb + t];
    }
    __syncthreads();
    int r = rb * 256 + threadIdx.x;
    int i = pb + r;
    float4 fi = sf[r];
    float bv[Kn]; int bix[Kn];
#pragma unroll
    for (int t = 0; t < Kn; t++) { bv[t] = 3.4e38f; bix[t] = 0; }
    for (int j = 0; j < NPt; j++) {
        float4 fj = sf[j];
        float s = ssq[j] - 2.f * (fi.x * fj.x + fi.y * fj.y + fi.z * fj.z + fi.w * fj.w);
        if (s < bv[Kn - 1]) {
            bv[Kn - 1] = s; bix[Kn - 1] = j;
#pragma unroll
            for (int t = Kn - 1; t > 0; --t) {
                if (bv[t] < bv[t - 1]) {
                    float tv = bv[t]; bv[t] = bv[t - 1]; bv[t - 1] = tv;
                    int ti = bix[t]; bix[t] = bix[t - 1]; bix[t - 1] = ti;
                }
            }
        }
    }
#pragma unroll
    for (int e = 0; e < Kn; e++) g_idx1[i * Kn + e] = pb + bix[e];
}

// ---------------- K2: EdgeConv1 (layers 2+3 per edge, warp-per-point) ----------------
__global__ void __launch_bounds__(256) k2_ec1(const float* __restrict__ w1b, const float* __restrict__ b1b,
                                              const float* __restrict__ w1c, const float* __restrict__ b1c) {
    extern __shared__ float smem[];
    float* ws1b = smem;                  // 4096
    float* ws1c = smem + 4096;           // 4096
    float* hb   = smem + 8192;           // 8 warps * 1280
    int tid = threadIdx.x, lane = tid & 31, w = tid >> 5;
    for (int t = tid; t < 1024; t += 256) {
        ((float4*)ws1b)[t] = ((const float4*)w1b)[t];
        ((float4*)ws1c)[t] = ((const float4*)w1c)[t];
    }
    __syncthreads();
    int i = blockIdx.x * 8 + w;
    float* h1 = hb + w * 1280;
    float* h2 = h1 + 640;
    float u0 = g_u[i * 64 + lane];
    float u1 = g_u[i * 64 + 32 + lane];
    int nbr[Kn];
#pragma unroll
    for (int e = 0; e < Kn; e++) nbr[e] = g_idx1[i * Kn + e];
#pragma unroll
    for (int e = 0; e < Kn; e++) {
        int j = nbr[e];
        h1[e * 64 + lane]      = lrelu(u0 + g_v[j * 64 + lane]);
        h1[e * 64 + 32 + lane] = lrelu(u1 + g_v[j * 64 + 32 + lane]);
    }
    __syncwarp();

    float acc0[Kn], acc1[Kn];
    // layer 2
    {
        float bb0 = b1b[lane], bb1 = b1b[32 + lane];
#pragma unroll
        for (int e = 0; e < Kn; e++) { acc0[e] = bb0; acc1[e] = bb1; }
#pragma unroll 4
        for (int kq = 0; kq < 16; kq++) {
            float w00 = ws1b[(4 * kq + 0) * 64 + lane];
            float w01 = ws1b[(4 * kq + 1) * 64 + lane];
            float w02 = ws1b[(4 * kq + 2) * 64 + lane];
            float w03 = ws1b[(4 * kq + 3) * 64 + lane];
            float w10 = ws1b[(4 * kq + 0) * 64 + 32 + lane];
            float w11 = ws1b[(4 * kq + 1) * 64 + 32 + lane];
            float w12 = ws1b[(4 * kq + 2) * 64 + 32 + lane];
            float w13 = ws1b[(4 * kq + 3) * 64 + 32 + lane];
#pragma unroll
            for (int e = 0; e < Kn; e++) {
                float4 h = *(const float4*)&h1[e * 64 + 4 * kq];
                acc0[e] += h.x * w00 + h.y * w01 + h.z * w02 + h.w * w03;
                acc1[e] += h.x * w10 + h.y * w11 + h.z * w12 + h.w * w13;
            }
        }
#pragma unroll
        for (int e = 0; e < Kn; e++) {
            h2[e * 64 + lane]      = lrelu(acc0[e]);
            h2[e * 64 + 32 + lane] = lrelu(acc1[e]);
        }
    }
    __syncwarp();
    // layer 3 + sum over edges
    {
        float bc0 = b1c[lane], bc1 = b1c[32 + lane];
#pragma unroll
        for (int e = 0; e < Kn; e++) { acc0[e] = bc0; acc1[e] = bc1; }
#pragma unroll 4
        for (int kq = 0; kq < 16; kq++) {
            float w00 = ws1c[(4 * kq + 0) * 64 + lane];
            float w01 = ws1c[(4 * kq + 1) * 64 + lane];
            float w02 = ws1c[(4 * kq + 2) * 64 + lane];
            float w03 = ws1c[(4 * kq + 3) * 64 + lane];
            float w10 = ws1c[(4 * kq + 0) * 64 + 32 + lane];
            float w11 = ws1c[(4 * kq + 1) * 64 + 32 + lane];
            float w12 = ws1c[(4 * kq + 2) * 64 + 32 + lane];
            float w13 = ws1c[(4 * kq + 3) * 64 + 32 + lane];
#pragma unroll
            for (int e = 0; e < Kn; e++) {
                float4 h = *(const float4*)&h2[e * 64 + 4 * kq];
                acc0[e] += h.x * w00 + h.y * w01 + h.z * w02 + h.w * w03;
                acc1[e] += h.x * w10 + h.y * w11 + h.z * w12 + h.w * w13;
            }
        }
    }
    float s0 = 0.f, s1 = 0.f;
#pragma unroll
    for (int e = 0; e < Kn; e++) { s0 += lrelu(acc0[e]); s1 += lrelu(acc1[e]); }
    g_x1[i * 64 + lane] = s0;
    g_x1[i * 64 + 32 + lane] = s1;
    float sq = s0 * s0 + s1 * s1;
#pragma unroll
    for (int off = 16; off; off >>= 1) sq += __shfl_xor_sync(0xffffffffu, sq, off);
    if (lane == 0) g_sq1[i] = sq;
}

// ---------------- K3: KNN on 64-dim x1 (thread-per-row, broadcast smem cols) ----------------
__global__ void __launch_bounds__(256) k3_knn2() {
    extern __shared__ float smem[];
    float* scol = smem;            // 256*64
    float* ssqc = smem + 256 * 64; // 256
    int b = blockIdx.x >> 2, rb = blockIdx.x & 3;
    int pb = b * NPt;
    int r = rb * 256 + threadIdx.x;
    int i = pb + r;
    float4 fi[16];
#pragma unroll
    for (int t = 0; t < 16; t++) fi[t] = ((const float4*)g_x1)[i * 16 + t];
    float bv[Kn]; int bix[Kn];
#pragma unroll
    for (int t = 0; t < Kn; t++) { bv[t] = 3.4e38f; bix[t] = 0; }

    for (int ch = 0; ch < 4; ch++) {
        int cb = ch * 256;
        __syncthreads();
        for (int t = threadIdx.x; t < 256 * 16; t += 256)
            ((float4*)scol)[t] = ((const float4*)g_x1)[(pb + cb) * 16 + t];
        if (threadIdx.x < 256) ssqc[threadIdx.x] = g_sq1[pb + cb + threadIdx.x];
        __syncthreads();
        for (int j = 0; j < 256; j++) {
            const float4* fj = (const float4*)&scol[j * 64];
            float a0 = 0.f, a1 = 0.f, a2 = 0.f, a3 = 0.f;
#pragma unroll
            for (int t = 0; t < 16; t += 4) {
                float4 c0 = fj[t], c1 = fj[t + 1], c2 = fj[t + 2], c3 = fj[t + 3];
                a0 += fi[t].x * c0.x + fi[t].y * c0.y + fi[t].z * c0.z + fi[t].w * c0.w;
                a1 += fi[t + 1].x * c1.x + fi[t + 1].y * c1.y + fi[t + 1].z * c1.z + fi[t + 1].w * c1.w;
                a2 += fi[t + 2].x * c2.x + fi[t + 2].y * c2.y + fi[t + 2].z * c2.z + fi[t + 2].w * c2.w;
                a3 += fi[t + 3].x * c3.x + fi[t + 3].y * c3.y + fi[t + 3].z * c3.z + fi[t + 3].w * c3.w;
            }
            float s = ssqc[j] - 2.f * ((a0 + a1) + (a2 + a3));
            if (s < bv[Kn - 1]) {
                bv[Kn - 1] = s; bix[Kn - 1] = cb + j;
#pragma unroll
                for (int t = Kn - 1; t > 0; --t) {
                    if (bv[t] < bv[t - 1]) {
                        float tv = bv[t]; bv[t] = bv[t - 1]; bv[t - 1] = tv;
                        int ti = bix[t]; bix[t] = bix[t - 1]; bix[t - 1] = ti;
                    }
                }
            }
        }
    }
#pragma unroll
    for (int e = 0; e < Kn; e++) g_idx2[i * Kn + e] = pb + bix[e];
}

// ---------------- K4: EdgeConv2 per-point P,Q (factored GEMV) ----------------
__global__ void __launch_bounds__(256) k4_pq(const float* __restrict__ w2, const float* __restrict__ b2) {
    extern __shared__ float smem[];
    float* wd  = smem;           // 64*128 : Wtop - Wbot
    float* wbm = smem + 8192;    // 64*128 : Wbot
    float* xb  = smem + 16384;   // 8 warps * 64
    int tid = threadIdx.x, lane = tid & 31, w = tid >> 5;
    for (int t = tid; t < 8192; t += 256) {
        int k = t >> 7, c = t & 127;
        float top = w2[k * 128 + c];
        float bot = w2[(64 + k) * 128 + c];
        wd[t] = top - bot;
        wbm[t] = bot;
    }
    __syncthreads();
    float4 bP = ((const float4*)b2)[lane];
    int base = blockIdx.x * 256 + w * 32;
    for (int pp = 0; pp < 32; pp++) {
        int i = base + pp;
        xb[w * 64 + lane]      = g_x1[i * 64 + lane];
        xb[w * 64 + 32 + lane] = g_x1[i * 64 + 32 + lane];
        __syncwarp();
        float4 accP = bP;
        float4 accQ = make_float4(0.f, 0.f, 0.f, 0.f);
#pragma unroll 4
        for (int kq = 0; kq < 16; kq++) {
            float4 xv = *(const float4*)&xb[w * 64 + 4 * kq];
            float xs[4] = {xv.x, xv.y, xv.z, xv.w};
#pragma unroll
            for (int t = 0; t < 4; t++) {
                float4 wdv = *(const float4*)&wd[(4 * kq + t) * 128 + 4 * lane];
                float4 wbv = *(const float4*)&wbm[(4 * kq + t) * 128 + 4 * lane];
                accP.x += xs[t] * wdv.x; accP.y += xs[t] * wdv.y; accP.z += xs[t] * wdv.z; accP.w += xs[t] * wdv.w;
                accQ.x += xs[t] * wbv.x; accQ.y += xs[t] * wbv.y; accQ.z += xs[t] * wbv.z; accQ.w += xs[t] * wbv.w;
            }
        }
        ((float4*)g_P)[i * 32 + lane] = accP;
        ((float4*)g_Q)[i * 32 + lane] = accQ;
        __syncwarp();
    }
}

// ---------------- K5: EdgeConv2 edge sum + per-(batch,sub) feature sums ----------------
__global__ void __launch_bounds__(256) k5_sum() {
    __shared__ float red[8][192];
    int b = blockIdx.x >> 2, sub = blockIdx.x & 3;
    int lane = threadIdx.x & 31, w = threadIdx.x >> 5;
    int i0 = b * NPt + sub * 256 + w * 32;
    float4 s2 = make_float4(0.f, 0.f, 0.f, 0.f);
    float sx0 = 0.f, sx1 = 0.f;
    for (int pp = 0; pp < 32; pp++) {
        int i = i0 + pp;
        int nbr[Kn];
#pragma unroll
        for (int e = 0; e < Kn; e++) nbr[e] = g_idx2[i * Kn + e];
        float4 Pv = ((const float4*)g_P)[i * 32 + lane];
        float4 a = make_float4(0.f, 0.f, 0.f, 0.f);
#pragma unroll
        for (int e = 0; e < Kn; e++) {
            float4 qv = ((const float4*)g_Q)[nbr[e] * 32 + lane];
            a.x += lrelu(Pv.x + qv.x);
            a.y += lrelu(Pv.y + qv.y);
            a.z += lrelu(Pv.z + qv.z);
            a.w += lrelu(Pv.w + qv.w);
        }
        s2.x += a.x; s2.y += a.y; s2.z += a.z; s2.w += a.w;
        float2 xv = *(const float2*)&g_x1[i * 64 + 2 * lane];
        sx0 += xv.x; sx1 += xv.y;
    }
    red[w][2 * lane] = sx0;
    red[w][2 * lane + 1] = sx1;
    red[w][64 + 4 * lane + 0] = s2.x;
    red[w][64 + 4 * lane + 1] = s2.y;
    red[w][64 + 4 * lane + 2] = s2.z;
    red[w][64 + 4 * lane + 3] = s2.w;
    __syncthreads();
    for (int t = threadIdx.x; t < 192; t += 256) {
        float s = 0.f;
#pragma unroll
        for (int ww = 0; ww < 8; ww++) s += red[ww][t];
        g_msum[blockIdx.x * 192 + t] = s;
    }
}

// ---------------- K7: head MLP (mean -> wl -> wm1 -> wm2 -> wm3) ----------------
__global__ void __launch_bounds__(256) k7_head(const float* __restrict__ wl, const float* __restrict__ bl,
                                               const float* __restrict__ wm1, const float* __restrict__ bm1,
                                               const float* __restrict__ wm2, const float* __restrict__ bm2,
                                               const float* __restrict__ wm3, const float* __restrict__ bm3,
                                               float* __restrict__ out) {
    __shared__ float sm[192];
    __shared__ float h0[1024];
    __shared__ float h1[512];
    __shared__ float h2[256];
    int b = blockIdx.x, tid = threadIdx.x;
    for (int t = tid; t < 192; t += 256) {
        float s = g_msum[(b * 4 + 0) * 192 + t] + g_msum[(b * 4 + 1) * 192 + t]
                + g_msum[(b * 4 + 2) * 192 + t] + g_msum[(b * 4 + 3) * 192 + t];
        sm[t] = s * (1.f / 1024.f);
    }
    __syncthreads();
    for (int o = tid; o < 1024; o += 256) {
        float a0 = 0.f, a1 = 0.f;
        for (int k = 0; k < 192; k += 2) {
            a0 += sm[k] * wl[k * 1024 + o];
            a1 += sm[k + 1] * wl[(k + 1) * 1024 + o];
        }
        h0[o] = a0 + a1 + bl[o];
    }
    __syncthreads();
    for (int o = tid; o < 512; o += 256) {
        float a0 = 0.f, a1 = 0.f, a2 = 0.f, a3 = 0.f;
        for (int k = 0; k < 1024; k += 4) {
            a0 += h0[k] * wm1[k * 512 + o];
            a1 += h0[k + 1] * wm1[(k + 1) * 512 + o];
            a2 += h0[k + 2] * wm1[(k + 2) * 512 + o];
            a3 += h0[k + 3] * wm1[(k + 3) * 512 + o];
        }
        h1[o] = lrelu(a0 + a1 + a2 + a3 + bm1[o]);
    }
    __syncthreads();
    if (tid < 256) {
        float a0 = 0.f, a1 = 0.f, a2 = 0.f, a3 = 0.f;
        for (int k = 0; k < 512; k += 4) {
            a0 += h1[k] * wm2[k * 256 + tid];
            a1 += h1[k + 1] * wm2[(k + 1) * 256 + tid];
            a2 += h1[k + 2] * wm2[(k + 2) * 256 + tid];
            a3 += h1[k + 3] * wm2[(k + 3) * 256 + tid];
        }
        h2[tid] = lrelu(a0 + a1 + a2 + a3 + bm2[tid]);
    }
    __syncthreads();
    if (tid < 3) {
        float a = bm3[tid];
        for (int k = 0; k < 256; k++) a += h2[k] * wm3[k * 3 + tid];
        out[b * 3 + tid] = a;
    }
}

// ---------------- launch ----------------
extern "C" void kernel_launch(void* const* d_in, const int* in_sizes, int n_in,
                              void* d_out, int out_size) {
    const float* x   = (const float*)d_in[0];
    const float* pos = (const float*)d_in[1];
    // d_in[2] = batch (int32) — layout is deterministic (b = i / 1024), unused
    const float* w1a = (const float*)d_in[3];
    const float* b1a = (const float*)d_in[4];
    const float* w1b = (const float*)d_in[5];
    const float* b1b = (const float*)d_in[6];
    const float* w1c = (const float*)d_in[7];
    const float* b1c = (const float*)d_in[8];
    const float* w2  = (const float*)d_in[9];
    const float* b2  = (const float*)d_in[10];
    const float* wl  = (const float*)d_in[11];
    const float* bl  = (const float*)d_in[12];
    const float* wm1 = (const float*)d_in[13];
    const float* bm1 = (const float*)d_in[14];
    const float* wm2 = (const float*)d_in[15];
    const float* bm2 = (const float*)d_in[16];
    const float* wm3 = (const float*)d_in[17];
    const float* bm3 = (const float*)d_in[18];
    float* out = (float*)d_out;

    cudaFuncSetAttribute(k2_ec1,  cudaFuncAttributeMaxDynamicSharedMemorySize, 73728);
    cudaFuncSetAttribute(k3_knn2, cudaFuncAttributeMaxDynamicSharedMemorySize, 66560);
    cudaFuncSetAttribute(k4_pq,   cudaFuncAttributeMaxDynamicSharedMemorySize, 67584);

    k0_pre<<<Nt / 8, 256>>>(x, pos, w1a, b1a);
    k1_knn1<<<Bt * 4, 256>>>();
    k2_ec1<<<Nt / 8, 256, 73728>>>(w1b, b1b, w1c, b1c);
    k3_knn2<<<Bt * 4, 256, 66560>>>();
    k4_pq<<<Nt / 256, 256, 67584>>>(w2, b2);
    k5_sum<<<Bt * 4, 256>>>();
    k7_head<<<Bt, 256>>>(wl, bl, wm1, bm1, wm2, bm2, wm3, bm3, out);
}